// round 6
// baseline (speedup 1.0000x reference)
#include <cuda_runtime.h>
#include <cuda_bf16.h>

// Problem constants
#define BB    32
#define NN    2048
#define KK    16
#define FIN   32
#define FOUT  64
#define TOTAL (BB * NN)          // 65536 nodes
#define ROW4  (FOUT / 4)         // 16 float4 per feature row

// Scratch (device globals: allocation-free rule).
__device__ float4 g_a[TOTAL * ROW4];   // a_i = x_i @ (W1 - W2) + b_edge
__device__ float4 g_c[TOTAL * ROW4];   // c_j = x_j @ W2
__device__ float4 g_s[TOTAL * ROW4];   // skip_i = relu(x_i @ W_nn + b_nn)
__device__ float4 g_spos[TOTAL];       // per-batch x-sorted (x,y,z,|p|^2)
__device__ int    g_sidx[TOTAL];       // sorted rank -> original global row
__device__ int    g_nb[TOTAL * KK];    // per original row: 16 neighbor rows

__device__ __forceinline__ float4 f4fma(float s, float4 w, float4 a) {
    a.x = __fmaf_rn(s, w.x, a.x);
    a.y = __fmaf_rn(s, w.y, a.y);
    a.z = __fmaf_rn(s, w.z, a.z);
    a.w = __fmaf_rn(s, w.w, a.w);
    return a;
}
__device__ __forceinline__ float4 f4max(float4 a, float4 b) {
    return make_float4(fmaxf(a.x, b.x), fmaxf(a.y, b.y),
                       fmaxf(a.z, b.z), fmaxf(a.w, b.w));
}

// Squared distance with a FIXED op sequence (all uses must agree bitwise).
__device__ __forceinline__ float dist2(float4 p, float4 q) {
    float dot = __fmaf_rn(p.x, q.x, __fmaf_rn(p.y, q.y, __fmul_rn(p.z, q.z)));
    return __fmaf_rn(-2.0f, dot, __fadd_rn(p.w, q.w));
}

// Sorted-16 insertion chain (caller gates with d < s[15]).
__device__ __forceinline__ void insert16(float (&s)[KK], float d) {
    float t = d;
#pragma unroll
    for (int q = 0; q < KK; q++) {
        float lo = fminf(s[q], t);
        t        = fmaxf(s[q], t);
        s[q]     = lo;
    }
}

// ---------------------------------------------------------------------------
// Kernel 0: per-batch bitonic sort of points by x. One block per batch.
// ---------------------------------------------------------------------------
__global__ __launch_bounds__(512)
void sort_kernel(const float* __restrict__ pos)
{
    __shared__ float key[NN];
    __shared__ int   val[NN];

    int tid  = threadIdx.x;
    int base = blockIdx.x * NN;

    for (int t = tid; t < NN; t += 512) {
        key[t] = pos[(base + t) * 3 + 0];
        val[t] = t;
    }

    for (int k = 2; k <= NN; k <<= 1) {
        for (int j = k >> 1; j > 0; j >>= 1) {
            __syncthreads();
            for (int t = tid; t < NN; t += 512) {
                int ixj = t ^ j;
                if (ixj > t) {
                    bool up = ((t & k) == 0);
                    float a = key[t], b = key[ixj];
                    if ((a > b) == up) {
                        key[t] = b; key[ixj] = a;
                        int tv = val[t]; val[t] = val[ixj]; val[ixj] = tv;
                    }
                }
            }
        }
    }
    __syncthreads();

    for (int t = tid; t < NN; t += 512) {
        int o = val[t];
        int g = base + o;
        float p0 = pos[g * 3 + 0];
        float p1 = pos[g * 3 + 1];
        float p2 = pos[g * 3 + 2];
        float sq = __fmaf_rn(p0, p0, __fmaf_rn(p1, p1, __fmul_rn(p2, p2)));
        g_spos[base + t] = make_float4(p0, p1, p2, sq);
        g_sidx[base + t] = g;
    }
}

// ---------------------------------------------------------------------------
// Kernel 1: per-node projections a, c, skip. One thread per node.
// ---------------------------------------------------------------------------
__global__ __launch_bounds__(128)
void proj_kernel(const float* __restrict__ x,
                 const float* __restrict__ W_edge,
                 const float* __restrict__ b_edge,
                 const float* __restrict__ W_nn,
                 const float* __restrict__ b_nn)
{
    __shared__ float sWd[FIN * FOUT];   // W1 - W2
    __shared__ float sW2[FIN * FOUT];   // W2
    __shared__ float sWn[FIN * FOUT];   // W_nn
    __shared__ float sbe[FOUT];
    __shared__ float sbn[FOUT];

    int tid = threadIdx.x;
    for (int t = tid; t < FIN * FOUT; t += 128) {
        float w1 = W_edge[t];
        float w2 = W_edge[FIN * FOUT + t];
        sWd[t] = w1 - w2;
        sW2[t] = w2;
        sWn[t] = W_nn[t];
    }
    if (tid < FOUT) { sbe[tid] = b_edge[tid]; sbn[tid] = b_nn[tid]; }
    __syncthreads();

    int node = blockIdx.x * 128 + tid;

    float xr[FIN];
    const float4* xp = (const float4*)(x + node * FIN);
#pragma unroll
    for (int q = 0; q < FIN / 4; q++) {
        float4 v = xp[q];
        xr[4 * q + 0] = v.x; xr[4 * q + 1] = v.y;
        xr[4 * q + 2] = v.z; xr[4 * q + 3] = v.w;
    }

    int rowb = node * ROW4;
#pragma unroll 1
    for (int fc = 0; fc < FOUT; fc += 4) {
        float4 aA = *(const float4*)&sbe[fc];
        float4 aC = make_float4(0.f, 0.f, 0.f, 0.f);
        float4 aS = *(const float4*)&sbn[fc];
#pragma unroll
        for (int r = 0; r < FIN; r++) {
            float xv = xr[r];
            aA = f4fma(xv, *(const float4*)&sWd[r * FOUT + fc], aA);
            aC = f4fma(xv, *(const float4*)&sW2[r * FOUT + fc], aC);
            aS = f4fma(xv, *(const float4*)&sWn[r * FOUT + fc], aS);
        }
        aS.x = fmaxf(aS.x, 0.f); aS.y = fmaxf(aS.y, 0.f);
        aS.z = fmaxf(aS.z, 0.f); aS.w = fmaxf(aS.w, 0.f);
        g_a[rowb + (fc >> 2)] = aA;
        g_c[rowb + (fc >> 2)] = aC;
        g_s[rowb + (fc >> 2)] = aS;
    }
}

// ---------------------------------------------------------------------------
// Kernel 2: exact KNN in x-sorted order with early exit.
// 2 threads per point: tid<256 scans right (ascending rank), tid>=256 scans
// left. Each side keeps its own exact top-16; bitonic 16-merge in smem gives
// the global 16th-smallest distance t16. Pass 2 re-scans each side (same
// early-exit vs t16) and writes neighbor ORIGINAL row ids via a shared
// per-point atomic counter. Early-exit bound: true d2 >= dx^2, and our
// computed d2 deviates < ~1e-5 absolute, so break at dx^2 > thr + 1e-3.
// ---------------------------------------------------------------------------
__global__ __launch_bounds__(512)
void knn_kernel()
{
    __shared__ float mbuf[256 * 17];   // padded (bank-conflict-free)
    __shared__ float thr[256];
    __shared__ int   cnt[256];

    int tid   = threadIdx.x;
    int idx   = tid & 255;
    bool rightSide = (tid < 256);
    int batch = blockIdx.x >> 3;
    int base  = batch * NN;
    int r     = ((blockIdx.x & 7) << 8) + idx;

    float4 pi = g_spos[base + r];
    float pix = pi.x;

    float s[KK];
#pragma unroll
    for (int q = 0; q < KK; q++) s[q] = 3.0e38f;

    // ---- Pass 1: one-sided exact top-16 with early exit ----
    if (rightSide) {
        for (int j = r + 1; j < NN; j++) {
            float4 q4 = g_spos[base + j];
            float dx = q4.x - pix;
            if (__fmul_rn(dx, dx) > s[KK - 1] + 1e-3f) break;
            float d = dist2(pi, q4);
            if (d < s[KK - 1]) insert16(s, d);
        }
    } else {
        for (int j = r - 1; j >= 0; j--) {
            float4 q4 = g_spos[base + j];
            float dx = pix - q4.x;
            if (__fmul_rn(dx, dx) > s[KK - 1] + 1e-3f) break;
            float d = dist2(pi, q4);
            if (d < s[KK - 1]) insert16(s, d);
        }
    }

    // ---- Merge the two sorted 16-lists -> t16 (16th smallest of union) ----
    if (!rightSide) {
#pragma unroll
        for (int q = 0; q < KK; q++) mbuf[idx * 17 + q] = s[q];
        cnt[idx] = 0;
    }
    __syncthreads();
    if (rightSide) {
        float t = -3.0e38f;
#pragma unroll
        for (int q = 0; q < KK; q++) {
            float c = fminf(s[q], mbuf[idx * 17 + (KK - 1 - q)]);
            t = fmaxf(t, c);
        }
        thr[idx] = t;
    }
    __syncthreads();
    float t16 = thr[idx];
    int orig_i = g_sidx[base + r];

    // ---- Pass 2: collect neighbor ids (d <= t16), same early exit ----
    if (rightSide) {
        for (int j = r + 1; j < NN; j++) {
            float4 q4 = g_spos[base + j];
            float dx = q4.x - pix;
            if (__fmul_rn(dx, dx) > t16 + 1e-3f) break;
            float d = dist2(pi, q4);
            if (d <= t16) {
                int slot = atomicAdd(&cnt[idx], 1);
                if (slot < KK) g_nb[orig_i * KK + slot] = g_sidx[base + j];
            }
        }
    } else {
        for (int j = r - 1; j >= 0; j--) {
            float4 q4 = g_spos[base + j];
            float dx = pix - q4.x;
            if (__fmul_rn(dx, dx) > t16 + 1e-3f) break;
            float d = dist2(pi, q4);
            if (d <= t16) {
                int slot = atomicAdd(&cnt[idx], 1);
                if (slot < KK) g_nb[orig_i * KK + slot] = g_sidx[base + j];
            }
        }
    }
}

// ---------------------------------------------------------------------------
// Kernel 3: aggregation. 4 threads per node, each handles 16 output features
// (4 float4): cmax[f] = max_k c_{nb_k}[f]; out = relu(a+cmax)+skip.
// ---------------------------------------------------------------------------
__global__ __launch_bounds__(256)
void agg_kernel(float4* __restrict__ out)
{
    int g = blockIdx.x * 256 + threadIdx.x;   // 262144 threads total
    int i = g >> 2;
    int q = (g & 3) << 2;                     // float4 offset: 0,4,8,12

    const int4* nb4 = (const int4*)&g_nb[i * KK];
    int4 n0 = nb4[0], n1 = nb4[1], n2 = nb4[2], n3 = nb4[3];
    int ids[KK];
    ids[0]  = n0.x; ids[1]  = n0.y; ids[2]  = n0.z; ids[3]  = n0.w;
    ids[4]  = n1.x; ids[5]  = n1.y; ids[6]  = n1.z; ids[7]  = n1.w;
    ids[8]  = n2.x; ids[9]  = n2.y; ids[10] = n2.z; ids[11] = n2.w;
    ids[12] = n3.x; ids[13] = n3.y; ids[14] = n3.z; ids[15] = n3.w;

    float4 m0 = make_float4(-3e38f, -3e38f, -3e38f, -3e38f);
    float4 m1 = m0, m2 = m0, m3 = m0;
#pragma unroll
    for (int k = 0; k < KK; k++) {
        const float4* cp = &g_c[ids[k] * ROW4 + q];
        m0 = f4max(m0, cp[0]);
        m1 = f4max(m1, cp[1]);
        m2 = f4max(m2, cp[2]);
        m3 = f4max(m3, cp[3]);
    }

    int irow = i * ROW4 + q;
    float4 mm[4] = {m0, m1, m2, m3};
#pragma unroll
    for (int u = 0; u < 4; u++) {
        float4 a  = g_a[irow + u];
        float4 sk = g_s[irow + u];
        float4 o;
        o.x = fmaxf(a.x + mm[u].x, 0.f) + sk.x;
        o.y = fmaxf(a.y + mm[u].y, 0.f) + sk.y;
        o.z = fmaxf(a.z + mm[u].z, 0.f) + sk.z;
        o.w = fmaxf(a.w + mm[u].w, 0.f) + sk.w;
        out[irow + u] = o;
    }
}

// ---------------------------------------------------------------------------
// Inputs (metadata order): x, pos, W_edge, b_edge, W_nn, b_nn, batch(unused)
// Output: float32 [65536, 64]
// ---------------------------------------------------------------------------
extern "C" void kernel_launch(void* const* d_in, const int* in_sizes, int n_in,
                              void* d_out, int out_size)
{
    const float* x      = (const float*)d_in[0];
    const float* pos    = (const float*)d_in[1];
    const float* W_edge = (const float*)d_in[2];
    const float* b_edge = (const float*)d_in[3];
    const float* W_nn   = (const float*)d_in[4];
    const float* b_nn   = (const float*)d_in[5];

    sort_kernel<<<BB, 512>>>(pos);
    proj_kernel<<<TOTAL / 128, 128>>>(x, W_edge, b_edge, W_nn, b_nn);
    knn_kernel<<<TOTAL / 256, 512>>>();
    agg_kernel<<<TOTAL * 4 / 256, 256>>>((float4*)d_out);
}

// round 8
// speedup vs baseline: 1.1060x; 1.1060x over previous
#include <cuda_runtime.h>
#include <cuda_bf16.h>

// Problem constants
#define BB    32
#define NN    2048
#define KK    16
#define FIN   32
#define FOUT  64
#define TOTAL (BB * NN)          // 65536 nodes
#define ROW4  (FOUT / 4)         // 16 float4 per feature row
#define CH    8                  // KNN scan chunk (MLP)

// Scratch (device globals: allocation-free rule).
__device__ float4 g_a[TOTAL * ROW4];   // a_i = x_i @ (W1 - W2) + b_edge
__device__ float4 g_c[TOTAL * ROW4];   // c_j = x_j @ W2
__device__ float4 g_s[TOTAL * ROW4];   // skip_i = relu(x_i @ W_nn + b_nn)
__device__ float4 g_spos[TOTAL];       // per-batch x-sorted (x,y,z,|p|^2)
__device__ int    g_sidx[TOTAL];       // sorted rank -> original global row
__device__ int    g_nb[TOTAL * KK];    // per original row: 16 neighbor rows

__device__ __forceinline__ float4 f4fma(float s, float4 w, float4 a) {
    a.x = __fmaf_rn(s, w.x, a.x);
    a.y = __fmaf_rn(s, w.y, a.y);
    a.z = __fmaf_rn(s, w.z, a.z);
    a.w = __fmaf_rn(s, w.w, a.w);
    return a;
}
__device__ __forceinline__ float4 f4max(float4 a, float4 b) {
    return make_float4(fmaxf(a.x, b.x), fmaxf(a.y, b.y),
                       fmaxf(a.z, b.z), fmaxf(a.w, b.w));
}

// Squared distance with a FIXED op sequence (all uses must agree bitwise).
__device__ __forceinline__ float dist2(float4 p, float4 q) {
    float dot = __fmaf_rn(p.x, q.x, __fmaf_rn(p.y, q.y, __fmul_rn(p.z, q.z)));
    return __fmaf_rn(-2.0f, dot, __fadd_rn(p.w, q.w));
}

// Sorted-16 insertion chain (caller gates with d < s[15]).
__device__ __forceinline__ void insert16(float (&s)[KK], float d) {
    float t = d;
#pragma unroll
    for (int q = 0; q < KK; q++) {
        float lo = fminf(s[q], t);
        t        = fmaxf(s[q], t);
        s[q]     = lo;
    }
}

// ---------------------------------------------------------------------------
// Kernel 0: per-batch bitonic sort of points by x. One block per batch.
// ---------------------------------------------------------------------------
__global__ __launch_bounds__(1024)
void sort_kernel(const float* __restrict__ pos)
{
    __shared__ float key[NN];
    __shared__ int   val[NN];

    int tid  = threadIdx.x;
    int base = blockIdx.x * NN;

    for (int t = tid; t < NN; t += 1024) {
        key[t] = pos[(base + t) * 3 + 0];
        val[t] = t;
    }

    for (int k = 2; k <= NN; k <<= 1) {
        for (int j = k >> 1; j > 0; j >>= 1) {
            __syncthreads();
#pragma unroll 1
            for (int t = tid; t < NN; t += 1024) {
                int ixj = t ^ j;
                if (ixj > t) {
                    bool up = ((t & k) == 0);
                    float a = key[t], b = key[ixj];
                    if ((a > b) == up) {
                        key[t] = b; key[ixj] = a;
                        int tv = val[t]; val[t] = val[ixj]; val[ixj] = tv;
                    }
                }
            }
        }
    }
    __syncthreads();

    for (int t = tid; t < NN; t += 1024) {
        int o = val[t];
        int g = base + o;
        float p0 = pos[g * 3 + 0];
        float p1 = pos[g * 3 + 1];
        float p2 = pos[g * 3 + 2];
        float sq = __fmaf_rn(p0, p0, __fmaf_rn(p1, p1, __fmul_rn(p2, p2)));
        g_spos[base + t] = make_float4(p0, p1, p2, sq);
        g_sidx[base + t] = g;
    }
}

// ---------------------------------------------------------------------------
// Kernel 1: per-node projections a, c, skip. One thread per node.
// ---------------------------------------------------------------------------
__global__ __launch_bounds__(128)
void proj_kernel(const float* __restrict__ x,
                 const float* __restrict__ W_edge,
                 const float* __restrict__ b_edge,
                 const float* __restrict__ W_nn,
                 const float* __restrict__ b_nn)
{
    __shared__ float sWd[FIN * FOUT];   // W1 - W2
    __shared__ float sW2[FIN * FOUT];   // W2
    __shared__ float sWn[FIN * FOUT];   // W_nn
    __shared__ float sbe[FOUT];
    __shared__ float sbn[FOUT];

    int tid = threadIdx.x;
    for (int t = tid; t < FIN * FOUT; t += 128) {
        float w1 = W_edge[t];
        float w2 = W_edge[FIN * FOUT + t];
        sWd[t] = w1 - w2;
        sW2[t] = w2;
        sWn[t] = W_nn[t];
    }
    if (tid < FOUT) { sbe[tid] = b_edge[tid]; sbn[tid] = b_nn[tid]; }
    __syncthreads();

    int node = blockIdx.x * 128 + tid;

    float xr[FIN];
    const float4* xp = (const float4*)(x + node * FIN);
#pragma unroll
    for (int q = 0; q < FIN / 4; q++) {
        float4 v = xp[q];
        xr[4 * q + 0] = v.x; xr[4 * q + 1] = v.y;
        xr[4 * q + 2] = v.z; xr[4 * q + 3] = v.w;
    }

    int rowb = node * ROW4;
#pragma unroll 1
    for (int fc = 0; fc < FOUT; fc += 4) {
        float4 aA = *(const float4*)&sbe[fc];
        float4 aC = make_float4(0.f, 0.f, 0.f, 0.f);
        float4 aS = *(const float4*)&sbn[fc];
#pragma unroll
        for (int r = 0; r < FIN; r++) {
            float xv = xr[r];
            aA = f4fma(xv, *(const float4*)&sWd[r * FOUT + fc], aA);
            aC = f4fma(xv, *(const float4*)&sW2[r * FOUT + fc], aC);
            aS = f4fma(xv, *(const float4*)&sWn[r * FOUT + fc], aS);
        }
        aS.x = fmaxf(aS.x, 0.f); aS.y = fmaxf(aS.y, 0.f);
        aS.z = fmaxf(aS.z, 0.f); aS.w = fmaxf(aS.w, 0.f);
        g_a[rowb + (fc >> 2)] = aA;
        g_c[rowb + (fc >> 2)] = aC;
        g_s[rowb + (fc >> 2)] = aS;
    }
}

// ---------------------------------------------------------------------------
// Kernel 2: exact KNN in x-sorted order, CHUNKED early-exit scans.
// 2 threads per point on ADJACENT LANES: even lane scans right (ascending
// rank), odd lane scans left. Chunks of 8: batched loads (MLP=8), exit bound
// checked once per chunk on the chunk's farthest-x element (sound: sorted).
// The two exact sorted-16 lists merge via shfl_xor to t16 = 16th smallest of
// the union. Pass 2 rescans with the same chunking and bound t16 and collects
// the <=16 neighbor ORIGINAL rows via a per-point smem atomic counter.
// Early-exit margin: true d2 >= dx^2; computed d2 deviates < ~1e-4, so
// break only at dx^2 > bound + 1e-3 (conservative -> exact).
// ---------------------------------------------------------------------------
__global__ __launch_bounds__(256)
void knn_kernel()
{
    __shared__ int cnt[128];           // per-point pass-2 slot counters

    int tid   = threadIdx.x;
    int g     = blockIdx.x * 256 + tid;      // 131072 threads
    int p     = g >> 1;                      // point id (sorted space)
    int side  = g & 1;                       // 0 = right, 1 = left
    int batch = p >> 11;
    int base  = batch * NN;
    int r     = p & (NN - 1);

    float4 pi = g_spos[base + r];
    float pix = pi.x;

    float s[KK];
#pragma unroll
    for (int q = 0; q < KK; q++) s[q] = 3.0e38f;

    // ---- Pass 1: one-sided exact top-16, chunked early exit ----
    if (side == 0) {
        int j0 = r + 1;
        while (j0 < NN) {
            float dl[CH]; float xf;
#pragma unroll
            for (int u = 0; u < CH; u++) {
                int j  = j0 + u;
                int jc = j < NN - 1 ? j : NN - 1;
                float4 q4 = g_spos[base + jc];
                float d = dist2(pi, q4);
                dl[u] = (j < NN) ? d : 3.0e38f;
                if (u == CH - 1) xf = q4.x;
            }
#pragma unroll
            for (int u = 0; u < CH; u++)
                if (dl[u] < s[KK - 1]) insert16(s, dl[u]);
            float dxf = xf - pix;
            if (__fmul_rn(dxf, dxf) > s[KK - 1] + 1e-3f) break;
            j0 += CH;
        }
    } else {
        int j0 = r - 1;
        while (j0 >= 0) {
            float dl[CH]; float xf;
#pragma unroll
            for (int u = 0; u < CH; u++) {
                int j  = j0 - u;
                int jc = j > 0 ? j : 0;
                float4 q4 = g_spos[base + jc];
                float d = dist2(pi, q4);
                dl[u] = (j >= 0) ? d : 3.0e38f;
                if (u == CH - 1) xf = q4.x;
            }
#pragma unroll
            for (int u = 0; u < CH; u++)
                if (dl[u] < s[KK - 1]) insert16(s, dl[u]);
            float dxf = pix - xf;
            if (__fmul_rn(dxf, dxf) > s[KK - 1] + 1e-3f) break;
            j0 -= CH;
        }
    }

    // ---- Merge pair lists via shfl: t16 = 16th smallest of union ----
    if (side == 1) cnt[tid >> 1] = 0;
    float t16 = -3.0e38f;
#pragma unroll
    for (int q = 0; q < KK; q++) {
        float o = __shfl_xor_sync(0xffffffffu, s[KK - 1 - q], 1);
        t16 = fmaxf(t16, fminf(s[q], o));
    }
    __syncthreads();

    int orig_i = g_sidx[base + r];
    float bnd  = t16 + 1e-3f;
    int   ci   = tid >> 1;

    // ---- Pass 2: collect neighbor ids (d <= t16), same chunking ----
    if (side == 0) {
        int j0 = r + 1;
        while (j0 < NN) {
            float dl[CH]; float xf;
#pragma unroll
            for (int u = 0; u < CH; u++) {
                int j  = j0 + u;
                int jc = j < NN - 1 ? j : NN - 1;
                float4 q4 = g_spos[base + jc];
                float d = dist2(pi, q4);
                dl[u] = (j < NN) ? d : 3.0e38f;
                if (u == CH - 1) xf = q4.x;
            }
#pragma unroll
            for (int u = 0; u < CH; u++) {
                if (dl[u] <= t16) {
                    int slot = atomicAdd(&cnt[ci], 1);
                    if (slot < KK) g_nb[orig_i * KK + slot] = g_sidx[base + j0 + u];
                }
            }
            float dxf = xf - pix;
            if (__fmul_rn(dxf, dxf) > bnd) break;
            j0 += CH;
        }
    } else {
        int j0 = r - 1;
        while (j0 >= 0) {
            float dl[CH]; float xf;
#pragma unroll
            for (int u = 0; u < CH; u++) {
                int j  = j0 - u;
                int jc = j > 0 ? j : 0;
                float4 q4 = g_spos[base + jc];
                float d = dist2(pi, q4);
                dl[u] = (j >= 0) ? d : 3.0e38f;
                if (u == CH - 1) xf = q4.x;
            }
#pragma unroll
            for (int u = 0; u < CH; u++) {
                if (dl[u] <= t16) {
                    int slot = atomicAdd(&cnt[ci], 1);
                    if (slot < KK) g_nb[orig_i * KK + slot] = g_sidx[base + j0 - u];
                }
            }
            float dxf = pix - xf;
            if (__fmul_rn(dxf, dxf) > bnd) break;
            j0 -= CH;
        }
    }
}

// ---------------------------------------------------------------------------
// Kernel 3: aggregation, coalesced. 16 lanes per node; lane q owns output
// float4 q. Neighbor ids broadcast within the 16-lane group via shfl so each
// g_c load instruction reads one 256B row segment (coalesced).
// ---------------------------------------------------------------------------
__global__ __launch_bounds__(256)
void agg_kernel(float4* __restrict__ out)
{
    int g = blockIdx.x * 256 + threadIdx.x;   // TOTAL*16 threads
    int i = g >> 4;                           // node
    int q = g & 15;                           // float4 lane within row

    int myid = g_nb[i * KK + q];              // lane q holds neighbor q (coalesced)

    float4 m = make_float4(-3e38f, -3e38f, -3e38f, -3e38f);
#pragma unroll
    for (int k = 0; k < KK; k++) {
        int idk = __shfl_sync(0xffffffffu, myid, k, 16);
        m = f4max(m, g_c[idk * ROW4 + q]);
    }

    int irow = i * ROW4 + q;
    float4 a  = g_a[irow];
    float4 sk = g_s[irow];
    float4 o;
    o.x = fmaxf(a.x + m.x, 0.f) + sk.x;
    o.y = fmaxf(a.y + m.y, 0.f) + sk.y;
    o.z = fmaxf(a.z + m.z, 0.f) + sk.z;
    o.w = fmaxf(a.w + m.w, 0.f) + sk.w;
    out[irow] = o;
}

// ---------------------------------------------------------------------------
// Inputs (metadata order): x, pos, W_edge, b_edge, W_nn, b_nn, batch(unused)
// Output: float32 [65536, 64]
// ---------------------------------------------------------------------------
extern "C" void kernel_launch(void* const* d_in, const int* in_sizes, int n_in,
                              void* d_out, int out_size)
{
    const float* x      = (const float*)d_in[0];
    const float* pos    = (const float*)d_in[1];
    const float* W_edge = (const float*)d_in[2];
    const float* b_edge = (const float*)d_in[3];
    const float* W_nn   = (const float*)d_in[4];
    const float* b_nn   = (const float*)d_in[5];

    sort_kernel<<<BB, 1024>>>(pos);
    proj_kernel<<<TOTAL / 128, 128>>>(x, W_edge, b_edge, W_nn, b_nn);
    knn_kernel<<<TOTAL * 2 / 256, 256>>>();
    agg_kernel<<<TOTAL * 16 / 256, 256>>>((float4*)d_out);
}